// round 2
// baseline (speedup 1.0000x reference)
#include <cuda_runtime.h>
#include <math.h>

#define Bv 2
#define Tv 2048
#define Dv 1024
#define Hv 16
#define HDv 64
#define Mv (Bv * Tv)   // 4096

// Scratch (allocation-free rule: __device__ globals)
__device__ float g_Q[Bv * Hv * Tv * HDv];   // [b,h,t,hd]
__device__ float g_K[Bv * Hv * Tv * HDv];
__device__ float g_V[Bv * Hv * Tv * HDv];
__device__ float g_AO[Bv * Tv * Dv];        // attention out, [b,t,h*HD+hd]
__device__ float g_QS[Bv * Hv * Tv * 3];
__device__ float g_CKV[Bv * Hv * Tv * 3];

// ---------------------------------------------------------------------------
// GEMM: C[m,n] = sum_k X[m,k] * W[n,k] + bias[n]
// M=4096, N=1024, K=1024. BM=BN=64, BK=16. 256 threads, 4x4 micro-tile.
// SPLIT: write to [b,h,t,hd] head-split layout; else row-major [m,n].
// ---------------------------------------------------------------------------
template <bool SPLIT>
__global__ __launch_bounds__(256) void gemm_proj(const float* __restrict__ X,
                                                 const float* __restrict__ W,
                                                 const float* __restrict__ bias,
                                                 float* __restrict__ out) {
    __shared__ float As[16][64];   // As[k][m]
    __shared__ float Bs[16][64];   // Bs[k][n]

    const int K = 1024;
    const int n0 = blockIdx.x * 64;
    const int m0 = blockIdx.y * 64;
    const int tid = threadIdx.x;
    const int tx = tid & 15;       // 0..15 -> n
    const int ty = tid >> 4;       // 0..15 -> m

    float acc[4][4];
#pragma unroll
    for (int i = 0; i < 4; i++)
#pragma unroll
        for (int j = 0; j < 4; j++) acc[i][j] = 0.0f;

    for (int k0 = 0; k0 < K; k0 += 16) {
        // load A tile (64 rows x 16 cols) and B tile (64 rows of W x 16 cols)
#pragma unroll
        for (int it = 0; it < 4; it++) {
            int idx = tid + it * 256;        // 0..1023
            int r = idx >> 4;                // 0..63
            int c = idx & 15;                // 0..15
            As[c][r] = X[(size_t)(m0 + r) * K + k0 + c];
            Bs[c][r] = W[(size_t)(n0 + r) * K + k0 + c];
        }
        __syncthreads();

#pragma unroll
        for (int kk = 0; kk < 16; kk++) {
            float a[4], b[4];
#pragma unroll
            for (int i = 0; i < 4; i++) a[i] = As[kk][ty * 4 + i];
#pragma unroll
            for (int j = 0; j < 4; j++) b[j] = Bs[kk][tx * 4 + j];
#pragma unroll
            for (int i = 0; i < 4; i++)
#pragma unroll
                for (int j = 0; j < 4; j++) acc[i][j] += a[i] * b[j];
        }
        __syncthreads();
    }

#pragma unroll
    for (int i = 0; i < 4; i++) {
        int m = m0 + ty * 4 + i;
#pragma unroll
        for (int j = 0; j < 4; j++) {
            int n = n0 + tx * 4 + j;
            float v = acc[i][j] + bias[n];
            if (SPLIT) {
                int b = m / Tv, t = m % Tv;
                int h = n / HDv, hd = n % HDv;
                out[(((size_t)(b * Hv + h) * Tv) + t) * HDv + hd] = v;
            } else {
                out[(size_t)m * Dv + n] = v;
            }
        }
    }
}

// ---------------------------------------------------------------------------
// STP: per (b,h,t) row, compute q_stp[3] and cross(k3, v3)[3]. One warp/row.
// ---------------------------------------------------------------------------
__global__ __launch_bounds__(256) void stp_kernel(const float* __restrict__ Wqs,
                                                  const float* __restrict__ bqs,
                                                  const float* __restrict__ Wks,
                                                  const float* __restrict__ bks,
                                                  const float* __restrict__ Wvs,
                                                  const float* __restrict__ bvs) {
    int warp = (blockIdx.x * blockDim.x + threadIdx.x) >> 5;
    int lane = threadIdx.x & 31;
    if (warp >= Bv * Hv * Tv) return;

    const float* q = g_Q + (size_t)warp * HDv;
    const float* k = g_K + (size_t)warp * HDv;
    const float* v = g_V + (size_t)warp * HDv;

    float q0 = q[lane], q1 = q[lane + 32];
    float k0 = k[lane], k1 = k[lane + 32];
    float v0 = v[lane], v1 = v[lane + 32];

    float qs[3], k3[3], v3[3];
#pragma unroll
    for (int c = 0; c < 3; c++) {
        float pq = q0 * Wqs[c * HDv + lane] + q1 * Wqs[c * HDv + lane + 32];
        float pk = k0 * Wks[c * HDv + lane] + k1 * Wks[c * HDv + lane + 32];
        float pv = v0 * Wvs[c * HDv + lane] + v1 * Wvs[c * HDv + lane + 32];
#pragma unroll
        for (int o = 16; o > 0; o >>= 1) {
            pq += __shfl_xor_sync(0xffffffffu, pq, o);
            pk += __shfl_xor_sync(0xffffffffu, pk, o);
            pv += __shfl_xor_sync(0xffffffffu, pv, o);
        }
        qs[c] = pq + bqs[c];
        k3[c] = pk + bks[c];
        v3[c] = pv + bvs[c];
    }

    if (lane == 0) {
        g_QS[(size_t)warp * 3 + 0] = qs[0];
        g_QS[(size_t)warp * 3 + 1] = qs[1];
        g_QS[(size_t)warp * 3 + 2] = qs[2];
        g_CKV[(size_t)warp * 3 + 0] = k3[1] * v3[2] - k3[2] * v3[1];
        g_CKV[(size_t)warp * 3 + 1] = k3[2] * v3[0] - k3[0] * v3[2];
        g_CKV[(size_t)warp * 3 + 2] = k3[0] * v3[1] - k3[1] * v3[0];
    }
}

// ---------------------------------------------------------------------------
// Flash-style attention. One thread per query row; K/V tiles of 32 in smem.
// scores = (q.k + q_stp . cross_kv) * temp ; online softmax ; acc += p*V.
// ---------------------------------------------------------------------------
#define KT 32

__global__ __launch_bounds__(128) void attn_kernel(const float* __restrict__ temp_p) {
    const int b = blockIdx.z;
    const int h = blockIdx.y;
    const int qrow = blockIdx.x * 128 + threadIdx.x;
    const int tid = threadIdx.x;
    const float temp = *temp_p;

    const size_t head_off = ((size_t)(b * Hv + h)) * Tv * HDv;
    const float4* Kp4 = (const float4*)(g_K + head_off);
    const float4* Vp4 = (const float4*)(g_V + head_off);
    const float4* Qp4 = (const float4*)(g_Q + head_off + (size_t)qrow * HDv);
    const float* QSp = g_QS + ((size_t)(b * Hv + h)) * Tv * 3;
    const float* CKVp = g_CKV + ((size_t)(b * Hv + h)) * Tv * 3;

    float4 q[16];
#pragma unroll
    for (int i = 0; i < 16; i++) q[i] = Qp4[i];
    const float qs0 = QSp[qrow * 3 + 0];
    const float qs1 = QSp[qrow * 3 + 1];
    const float qs2 = QSp[qrow * 3 + 2];

    float4 acc[16];
#pragma unroll
    for (int i = 0; i < 16; i++) acc[i] = make_float4(0.f, 0.f, 0.f, 0.f);
    float mval = -INFINITY;
    float lsum = 0.0f;

    __shared__ float4 Ks[KT][16];
    __shared__ float4 Vs[KT][16];
    __shared__ float Cs[KT][3];

    for (int kt = 0; kt < Tv; kt += KT) {
        // cooperative load: KT*16 float4 per tensor, 128 threads -> 4 each
#pragma unroll
        for (int it = 0; it < 4; it++) {
            int idx = tid + it * 128;     // 0..511
            int r = idx >> 4;
            int c = idx & 15;
            Ks[r][c] = Kp4[(size_t)(kt + r) * 16 + c];
            Vs[r][c] = Vp4[(size_t)(kt + r) * 16 + c];
        }
        if (tid < KT * 3) ((float*)Cs)[tid] = CKVp[kt * 3 + tid];
        __syncthreads();

        float sv[KT];
        float tmax = mval;
#pragma unroll
        for (int j = 0; j < KT; j++) {
            float s = 0.0f;
#pragma unroll
            for (int c = 0; c < 16; c++) {
                float4 kk = Ks[j][c];
                s += q[c].x * kk.x + q[c].y * kk.y + q[c].z * kk.z + q[c].w * kk.w;
            }
            s += qs0 * Cs[j][0] + qs1 * Cs[j][1] + qs2 * Cs[j][2];
            s *= temp;
            sv[j] = s;
            tmax = fmaxf(tmax, s);
        }

        const float scale = __expf(mval - tmax);   // 0 on first tile (mval=-inf)
        mval = tmax;
        lsum *= scale;
#pragma unroll
        for (int c = 0; c < 16; c++) {
            acc[c].x *= scale; acc[c].y *= scale; acc[c].z *= scale; acc[c].w *= scale;
        }
#pragma unroll
        for (int j = 0; j < KT; j++) {
            float p = __expf(sv[j] - mval);
            lsum += p;
#pragma unroll
            for (int c = 0; c < 16; c++) {
                float4 vv = Vs[j][c];
                acc[c].x += p * vv.x;
                acc[c].y += p * vv.y;
                acc[c].z += p * vv.z;
                acc[c].w += p * vv.w;
            }
        }
        __syncthreads();
    }

    const float inv = 1.0f / lsum;
    float4* o = (float4*)(g_AO + ((size_t)(b * Tv + qrow)) * Dv + h * HDv);
#pragma unroll
    for (int c = 0; c < 16; c++)
        o[c] = make_float4(acc[c].x * inv, acc[c].y * inv, acc[c].z * inv, acc[c].w * inv);
}

// ---------------------------------------------------------------------------
extern "C" void kernel_launch(void* const* d_in, const int* in_sizes, int n_in,
                              void* d_out, int out_size) {
    const float* x   = (const float*)d_in[0];
    const float* Wq  = (const float*)d_in[1];
    const float* bq  = (const float*)d_in[2];
    const float* Wk  = (const float*)d_in[3];
    const float* bk  = (const float*)d_in[4];
    const float* Wv  = (const float*)d_in[5];
    const float* bv  = (const float*)d_in[6];
    const float* Wo  = (const float*)d_in[7];
    const float* bo  = (const float*)d_in[8];
    const float* Wqs = (const float*)d_in[9];
    const float* bqs = (const float*)d_in[10];
    const float* Wks = (const float*)d_in[11];
    const float* bks = (const float*)d_in[12];
    const float* Wvs = (const float*)d_in[13];
    const float* bvs = (const float*)d_in[14];
    const float* temp = (const float*)d_in[15];

    float *gQ, *gK, *gV, *gAO;
    cudaGetSymbolAddress((void**)&gQ, g_Q);
    cudaGetSymbolAddress((void**)&gK, g_K);
    cudaGetSymbolAddress((void**)&gV, g_V);
    cudaGetSymbolAddress((void**)&gAO, g_AO);

    dim3 ggrid(Dv / 64, Mv / 64);   // (16, 64)
    gemm_proj<true><<<ggrid, 256>>>(x, Wq, bq, gQ);
    gemm_proj<true><<<ggrid, 256>>>(x, Wk, bk, gK);
    gemm_proj<true><<<ggrid, 256>>>(x, Wv, bv, gV);

    int nwarps = Bv * Hv * Tv;                 // 65536
    stp_kernel<<<nwarps / 8, 256>>>(Wqs, bqs, Wks, bks, Wvs, bvs);

    dim3 agrid(Tv / 128, Hv, Bv);              // (16, 16, 2)
    attn_kernel<<<agrid, 128>>>(temp);

    gemm_proj<false><<<ggrid, 256>>>(gAO, Wo, bo, (float*)d_out);
}